// round 17
// baseline (speedup 1.0000x reference)
#include <cuda_runtime.h>
#include <cuda_fp16.h>
#include <math.h>
#include <stdint.h>

#define NN 20000
#define NE 40000
#define NG 1000
#define NB 313   // src buckets of 64 nodes

// Scratch (static __device__ — no allocations allowed)
__device__ __half d_xh[(size_t)NN * 64];         // X in fp16, K padded
__device__ __half d_w2r[128 * 64 * 64];          // W2r[k][o][i] fp16, i padded
__device__ float d_Q[NN * 64];                   // b2 contribution per node
__device__ float d_xa[NN * 64];
__device__ float d_xb[NN * 64];
__device__ float d_agg[NN * 64];
__device__ float d_sums[NG * 64];
__device__ float d_cnt[NG];
// bucket-sorted edge order (built once, reused all layers)
__device__ int d_bcnt[NB + 8];
__device__ int d_btmp[NB + 8];
__device__ int d_boff[NB + 8];
__device__ int d_csrc[NE];
__device__ int d_cdst[NE];
__device__ float d_cea[(size_t)NE * 5];

__device__ __forceinline__ float eluf(float v) { return v > 0.f ? v : expm1f(v); }

__device__ __forceinline__ uint32_t smem_u32(const void* p) {
    uint32_t a;
    asm("{ .reg .u64 t; cvta.to.shared.u64 t, %1; cvt.u32.u64 %0, t; }" : "=r"(a) : "l"(p));
    return a;
}
__device__ __forceinline__ void ldm4(uint32_t& r0, uint32_t& r1, uint32_t& r2, uint32_t& r3,
                                     uint32_t addr) {
    asm volatile("ldmatrix.sync.aligned.m8n8.x4.shared.b16 {%0,%1,%2,%3}, [%4];"
                 : "=r"(r0), "=r"(r1), "=r"(r2), "=r"(r3) : "r"(addr));
}
__device__ __forceinline__ void mma16816(float* c, uint32_t a0, uint32_t a1, uint32_t a2,
                                         uint32_t a3, uint32_t b0, uint32_t b1) {
    asm volatile(
        "mma.sync.aligned.m16n8k16.row.col.f32.f16.f16.f32 "
        "{%0,%1,%2,%3}, {%4,%5,%6,%7}, {%8,%9}, {%0,%1,%2,%3};"
        : "+f"(c[0]), "+f"(c[1]), "+f"(c[2]), "+f"(c[3])
        : "r"(a0), "r"(a1), "r"(a2), "r"(a3), "r"(b0), "r"(b1));
}

__global__ void zerok(float* __restrict__ p, int n) {
    int i = blockIdx.x * blockDim.x + threadIdx.x;
    if (i < n) p[i] = 0.f;
}

// ---------------- bucket sort build (once) ----------------
__global__ void zerob_k(int* __restrict__ a, int* __restrict__ b) {
    int i = blockIdx.x * blockDim.x + threadIdx.x;
    if (i < NB + 8) { a[i] = 0; b[i] = 0; }
}
__global__ void histb_k(const int* __restrict__ src, int* __restrict__ cnt) {
    int e = blockIdx.x * blockDim.x + threadIdx.x;
    if (e < NE) atomicAdd(&cnt[src[e] >> 6], 1);
}
__global__ void scanb_k(const int* __restrict__ cnt, int* __restrict__ off) {
    __shared__ int sh[512];
    int t = threadIdx.x;
    int v = (t < NB) ? cnt[t] : 0;
    sh[t] = v;
    __syncthreads();
    for (int o = 1; o < 512; o <<= 1) {
        int u = (t >= o) ? sh[t - o] : 0;
        __syncthreads();
        sh[t] += u;
        __syncthreads();
    }
    if (t < NB) off[t] = sh[t] - v;
    if (t == NB - 1) off[NB] = sh[t];
}
__global__ void scatterb_k(const int* __restrict__ src, const int* __restrict__ dst,
                           const float* __restrict__ ea,
                           const int* __restrict__ off, int* __restrict__ tmp,
                           int* __restrict__ csrc, int* __restrict__ cdst,
                           float* __restrict__ cea) {
    int e = blockIdx.x * blockDim.x + threadIdx.x;
    if (e >= NE) return;
    int s = src[e];
    int b = s >> 6;
    int pos = off[b] + atomicAdd(&tmp[b], 1);
    csrc[pos] = s;
    cdst[pos] = dst[e];
#pragma unroll
    for (int a = 0; a < 5; a++) cea[(size_t)pos * 5 + a] = ea[(size_t)e * 5 + a];
}

// Merged conversions: idx < tw -> W2r build; else -> Xh build.
// W2r[k][o][i] = fp16(w2[k*mi*mo + i*mo + o]), i padded to KP.
__global__ void convWX_k(const float* __restrict__ w2, __half* __restrict__ W2r,
                         const float* __restrict__ X, __half* __restrict__ Xh,
                         int mi, int mo, int KP, int tw, int tot) {
    int idx = blockIdx.x * blockDim.x + threadIdx.x;
    if (idx >= tot) return;
    if (idx < tw) {
        int k = idx / (mo * KP);
        int r = idx - k * mo * KP;
        int o = r / KP, i = r - o * KP;
        W2r[idx] = (i < mi) ? __float2half(w2[(k * mi + i) * mo + o]) : __half(0.f);
    } else {
        int j = idx - tw;
        int n = j / KP, i = j - n * KP;
        Xh[j] = (i < mi) ? __float2half(X[n * mi + i]) : __half(0.f);
    }
}

// prep: agg[n,o] = bias[o] + sum_i X[n,i]*root[i,o]  (seed for atomics)
//       Q[n,o]   = sum_i X[n,i]*b2[i*mo+o]
__global__ void prep_k(const float* __restrict__ X, const float* __restrict__ root,
                       const float* __restrict__ bias, const float* __restrict__ b2,
                       float* __restrict__ agg, float* __restrict__ Q,
                       int mi, int mo, int tot) {
    int idx = blockIdx.x * blockDim.x + threadIdx.x;
    if (idx >= tot) return;
    int n = idx / mo, o = idx - n * mo;
    float r = bias[o], q = 0.f;
    for (int i = 0; i < mi; i++) {
        float xv = X[n * mi + i];
        r = fmaf(xv, root[i * mo + o], r);
        q = fmaf(xv, b2[i * mo + o], q);
    }
    agg[idx] = r;
    Q[idx] = q;
}

// ---------------- fused layer: per-slab P_k in smem + message accumulate ----
// Block b = bucket b: nodes [64b, 64b+64), edges boff[b]..boff[b+1].
// For each k: P_k[64, MO] = Xs @ W2r[k]^T (HMMA, fp32), then
// msgs[e][o] += h[e,k] * P_k[sloc[e]][o].  Flush msgs+Q -> agg atomically.
template<int MO, int KP>
__global__ void __launch_bounds__(256) fused_layer_k(
    const __half* __restrict__ Xh,      // [NN][KP]
    const __half* __restrict__ W2r,     // [128][MO][KP]
    const float* __restrict__ w1,       // [5][128]
    const float* __restrict__ b1p,      // [128]
    const float* __restrict__ Q,        // [NN][MO]
    const int* __restrict__ boff,
    const int* __restrict__ csrc, const int* __restrict__ cdst,
    const float* __restrict__ cea,      // [NE][5] (bucket-sorted)
    float* __restrict__ agg)
{
    constexpr int KPP = KP + 8;          // half pitch
    constexpr int POP = MO + 4;          // float pitch
    constexpr int MAXE = 160;
    constexpr int EL = 256 / MO;
    constexpr int KCH = KP / 16;
    constexpr int NW = MO / 2;           // cols per warp-half
    constexpr int NT8 = NW / 8;
    constexpr int NG16 = NW / 16;

    extern __shared__ __align__(16) char sm[];
    __half* Xs  = (__half*)sm;                          // 64*KPP
    __half* Wb  = Xs + 64 * KPP;                        // MO*KPP
    float*  Pk  = (float*)(Wb + MO * KPP);              // 64*POP
    float* msgs = Pk + 64 * POP;                        // MAXE*MO
    float* hk   = msgs + MAXE * MO;                     // MAXE
    float* eas  = hk + MAXE;                            // MAXE*5
    float* w1s  = eas + MAXE * 5;                       // 640
    float* b1s  = w1s + 640;                            // 128
    int*  sloc  = (int*)(b1s + 128);                    // MAXE
    int*  dste  = sloc + MAXE;                          // MAXE

    int b = blockIdx.x, tid = threadIdx.x;
    int n0 = b * 64;
    int warp = tid >> 5, lane = tid & 31;
    int p0 = boff[b], EB = boff[b + 1] - p0;

    // phase 0: Xs, w1, b1
    for (int t = tid; t < 64 * (KP / 8); t += 256) {
        int r = t / (KP / 8), j = t - r * (KP / 8);
        int n = n0 + r;
        int4 v = make_int4(0, 0, 0, 0);
        if (n < NN) v = *(const int4*)&Xh[(size_t)n * KP + j * 8];
        *(int4*)&Xs[r * KPP + j * 8] = v;
    }
    for (int t = tid; t < 640; t += 256) w1s[t] = w1[t];
    if (tid < 128) b1s[tid] = b1p[tid];
    __syncthreads();

    // A-fragments: each warp owns 16 rows (rg), covers NW cols (half).
    int rg = warp & 3, half = warp >> 2;
    int nbase = half * NW;
    uint32_t afr[KCH][4];
#pragma unroll
    for (int kc = 0; kc < KCH; kc++)
        ldm4(afr[kc][0], afr[kc][1], afr[kc][2], afr[kc][3],
             smem_u32(&Xs[(16 * rg + (lane & 15)) * KPP + kc * 16 + 8 * (lane >> 4)]));

    int o = tid % MO, el = tid / MO;

    for (int e0 = 0; e0 < EB; e0 += MAXE) {
        int Epass = min(EB - e0, MAXE);
        for (int t = tid; t < Epass; t += 256) {
            sloc[t] = csrc[p0 + e0 + t] - n0;
            dste[t] = cdst[p0 + e0 + t];
        }
        for (int t = tid; t < Epass * 5; t += 256)
            eas[t] = cea[(size_t)(p0 + e0) * 5 + t];
        for (int t = tid; t < Epass * MO; t += 256) msgs[t] = 0.f;
        __syncthreads();

        for (int k = 0; k < 128; k++) {
            // Wb slice + h for this k
            for (int t = tid; t < MO * (KP / 8); t += 256) {
                int r = t / (KP / 8), j = t - r * (KP / 8);
                *(int4*)&Wb[r * KPP + j * 8] =
                    *(const int4*)&W2r[((size_t)k * MO + r) * KP + j * 8];
            }
            if (tid < Epass) {
                float s = b1s[k];
#pragma unroll
                for (int a = 0; a < 5; a++) s = fmaf(eas[tid * 5 + a], w1s[a * 128 + k], s);
                hk[tid] = fmaxf(s, 0.f);
            }
            __syncthreads();

            // mma: Pk[64, MO]
            float c[NT8][4];
#pragma unroll
            for (int t = 0; t < NT8; t++) { c[t][0] = c[t][1] = c[t][2] = c[t][3] = 0.f; }
#pragma unroll
            for (int kc = 0; kc < KCH; kc++) {
#pragma unroll
                for (int g = 0; g < NG16; g++) {
                    uint32_t bb0, bb1, bb2, bb3;
                    int brow = nbase + 16 * g + (lane & 7) + ((lane & 16) ? 8 : 0);
                    int bcol = kc * 16 + ((lane & 8) ? 8 : 0);
                    ldm4(bb0, bb1, bb2, bb3, smem_u32(&Wb[brow * KPP + bcol]));
                    mma16816(c[2 * g],     afr[kc][0], afr[kc][1], afr[kc][2], afr[kc][3], bb0, bb1);
                    mma16816(c[2 * g + 1], afr[kc][0], afr[kc][1], afr[kc][2], afr[kc][3], bb2, bb3);
                }
            }
            int rr = lane >> 2, cc = 2 * (lane & 3);
#pragma unroll
            for (int t = 0; t < NT8; t++) {
                int col = nbase + 8 * t + cc;
                Pk[(16 * rg + rr) * POP + col]         = c[t][0];
                Pk[(16 * rg + rr) * POP + col + 1]     = c[t][1];
                Pk[(16 * rg + rr + 8) * POP + col]     = c[t][2];
                Pk[(16 * rg + rr + 8) * POP + col + 1] = c[t][3];
            }
            __syncthreads();

            // edge update
            for (int e = el; e < Epass; e += EL) {
                float h = hk[e];
                if (h != 0.f)
                    msgs[e * MO + o] = fmaf(h, Pk[sloc[e] * POP + o], msgs[e * MO + o]);
            }
            __syncthreads();
        }

        // flush
        for (int e = el; e < Epass; e += EL) {
            int gs = n0 + sloc[e];
            atomicAdd(&agg[dste[e] * MO + o], msgs[e * MO + o] + Q[(size_t)gs * MO + o]);
        }
        __syncthreads();
    }
}

// Xout = elu(agg)
__global__ void elu_k(const float* __restrict__ agg, float* __restrict__ Xout, int tot) {
    int idx = blockIdx.x * blockDim.x + threadIdx.x;
    if (idx < tot) Xout[idx] = eluf(agg[idx]);
}

__global__ void pool_k(const float* __restrict__ X, const int* __restrict__ batch,
                       float* __restrict__ sums, float* __restrict__ cnt) {
    int idx = blockIdx.x * blockDim.x + threadIdx.x;
    if (idx >= NN * 64) return;
    int n = idx >> 6, o = idx & 63;
    int g = batch[n];
    atomicAdd(&sums[g * 64 + o], X[idx]);
    if (o == 0) atomicAdd(&cnt[g], 1.f);
}

__global__ void fc_k(const float* __restrict__ sums, const float* __restrict__ cnt,
                     const float* __restrict__ w1, const float* __restrict__ bb1,
                     const float* __restrict__ w2, const float* __restrict__ bb2,
                     const float* __restrict__ w3, const float* __restrict__ bb3,
                     float* __restrict__ out) {
    int g = blockIdx.x, t = threadIdx.x;
    __shared__ float v[64], t1[32], t2[16];
    float c = fmaxf(cnt[g], 1.f);
    v[t] = sums[g * 64 + t] / c;
    __syncthreads();
    if (t < 32) {
        float s = bb1[t];
        for (int i = 0; i < 64; i++) s = fmaf(v[i], w1[i * 32 + t], s);
        t1[t] = eluf(s);
    }
    __syncthreads();
    if (t < 16) {
        float s = bb2[t];
        for (int i = 0; i < 32; i++) s = fmaf(t1[i], w2[i * 16 + t], s);
        t2[t] = eluf(s);
    }
    __syncthreads();
    if (t == 0) {
        float s = bb3[0];
        for (int i = 0; i < 16; i++) s = fmaf(t2[i], w3[i], s);
        out[g] = s;
    }
}

// smem size per instantiation
static int fused_smem(int MO, int KP) {
    int KPP = KP + 8, POP = MO + 4, MAXE = 160;
    return 64 * KPP * 2 + MO * KPP * 2 + 64 * POP * 4 + MAXE * MO * 4
         + MAXE * 4 + MAXE * 5 * 4 + 640 * 4 + 128 * 4 + MAXE * 8;
}

extern "C" void kernel_launch(void* const* d_in, const int* in_sizes, int n_in,
                              void* d_out, int out_size) {
    const float* x     = (const float*)d_in[0];
    const int*   ei    = (const int*)d_in[1];
    const float* ea    = (const float*)d_in[2];
    const int*   batch = (const int*)d_in[3];
    const float *W1[3], *B1[3], *W2[3], *B2[3], *ROOT[3], *BIAS[3];
    for (int l = 0; l < 3; l++) {
        int b = 4 + 6 * l;
        W1[l]   = (const float*)d_in[b + 0];
        B1[l]   = (const float*)d_in[b + 1];
        W2[l]   = (const float*)d_in[b + 2];
        B2[l]   = (const float*)d_in[b + 3];
        ROOT[l] = (const float*)d_in[b + 4];
        BIAS[l] = (const float*)d_in[b + 5];
    }
    const float* fc1w = (const float*)d_in[22];
    const float* fc1b = (const float*)d_in[23];
    const float* fc2w = (const float*)d_in[24];
    const float* fc2b = (const float*)d_in[25];
    const float* fc3w = (const float*)d_in[26];
    const float* fc3b = (const float*)d_in[27];
    float* out = (float*)d_out;

    float *Q, *xa, *xb, *agg, *sums, *cnt, *cea;
    __half *Xh, *W2r;
    int *bcnt, *btmp, *boff, *csrc, *cdst;
    cudaGetSymbolAddress((void**)&Xh, d_xh);
    cudaGetSymbolAddress((void**)&W2r, d_w2r);
    cudaGetSymbolAddress((void**)&Q, d_Q);
    cudaGetSymbolAddress((void**)&xa, d_xa);
    cudaGetSymbolAddress((void**)&xb, d_xb);
    cudaGetSymbolAddress((void**)&agg, d_agg);
    cudaGetSymbolAddress((void**)&sums, d_sums);
    cudaGetSymbolAddress((void**)&cnt, d_cnt);
    cudaGetSymbolAddress((void**)&bcnt, d_bcnt);
    cudaGetSymbolAddress((void**)&btmp, d_btmp);
    cudaGetSymbolAddress((void**)&boff, d_boff);
    cudaGetSymbolAddress((void**)&csrc, d_csrc);
    cudaGetSymbolAddress((void**)&cdst, d_cdst);
    cudaGetSymbolAddress((void**)&cea, d_cea);

    const int SM0 = fused_smem(32, 16);
    const int SM1 = fused_smem(64, 32);
    const int SM2 = fused_smem(64, 64);
    cudaFuncSetAttribute(fused_layer_k<32, 16>, cudaFuncAttributeMaxDynamicSharedMemorySize, SM0);
    cudaFuncSetAttribute(fused_layer_k<64, 32>, cudaFuncAttributeMaxDynamicSharedMemorySize, SM1);
    cudaFuncSetAttribute(fused_layer_k<64, 64>, cudaFuncAttributeMaxDynamicSharedMemorySize, SM2);

    const int* src = ei;
    const int* dst = ei + NE;
    const int MI[3] = {13, 32, 64};
    const int MO[3] = {32, 64, 64};
    const int KP[3] = {16, 32, 64};
    const float* xin = x;
    float* xouts[3] = {xa, xb, xa};

    for (int l = 0; l < 3; l++) {
        int mi = MI[l], mo = MO[l], kp = KP[l];
        int tq = NN * mo;
        int tw = 128 * mo * kp, ta = NN * kp, tc = tw + ta;
        if (l == 0) {
            zerob_k<<<2, 256>>>(bcnt, btmp);
            histb_k<<<(NE + 255) / 256, 256>>>(src, bcnt);
            scanb_k<<<1, 512>>>(bcnt, boff);
            scatterb_k<<<(NE + 255) / 256, 256>>>(src, dst, ea, boff, btmp, csrc, cdst, cea);
        }
        convWX_k<<<(tc + 255) / 256, 256>>>(W2[l], W2r, xin, Xh, mi, mo, kp, tw, tc);
        prep_k<<<(tq + 255) / 256, 256>>>(xin, ROOT[l], BIAS[l], B2[l], agg, Q, mi, mo, tq);
        if (l == 0)
            fused_layer_k<32, 16><<<NB, 256, SM0>>>(Xh, W2r, W1[l], B1[l], Q,
                                                    boff, csrc, cdst, cea, agg);
        else if (l == 1)
            fused_layer_k<64, 32><<<NB, 256, SM1>>>(Xh, W2r, W1[l], B1[l], Q,
                                                    boff, csrc, cdst, cea, agg);
        else
            fused_layer_k<64, 64><<<NB, 256, SM2>>>(Xh, W2r, W1[l], B1[l], Q,
                                                    boff, csrc, cdst, cea, agg);
        elu_k<<<(tq + 255) / 256, 256>>>(agg, xouts[l], tq);
        xin = xouts[l];
    }
    zerok<<<(NG * 64 + 255) / 256, 256>>>(sums, NG * 64);
    zerok<<<(NG + 255) / 256, 256>>>(cnt, NG);
    pool_k<<<(NN * 64 + 255) / 256, 256>>>(xin, batch, sums, cnt);
    fc_k<<<NG, 64>>>(sums, cnt, fc1w, fc1b, fc2w, fc2b, fc3w, fc3b, out);
}